// round 1
// baseline (speedup 1.0000x reference)
#include <cuda_runtime.h>
#include <math.h>

#define NT   2048      // B*T tokens
#define DD   1024      // model dim
#define EE   16        // experts
#define FF   512       // expert ffn dim
#define FSH  2048      // shared expert ffn dim

#define BM 64
#define BN 64
#define BK 16
#define LDSD 68        // padded smem lead (68*4B = 272B, 16B-aligned rows, conflict-reducing)

// ---------------- scratch (static device globals; no runtime allocation) ----------------
__device__ int   g_cnt[EE];
__device__ float g_load[EE];
__device__ int   g_tok[EE * NT];
__device__ float g_wt[EE * NT];
__device__ float g_gs[NT];
__device__ float g_H[(size_t)EE * NT * FF];   // expert hidden, per-expert packed rows
__device__ float g_Hs[(size_t)NT * FSH];      // shared-expert hidden

// ---------------------------------------------------------------------------------------
__global__ void zero_k() {
    int i = threadIdx.x;
    if (i < EE) { g_cnt[i] = 0; g_load[i] = 0.f; }
}

// Router: one block per token. Computes logits [16], softmax, top-2, normalized weights,
// per-expert gather lists, load accumulation for aux loss, and the shared sigmoid gate.
__global__ __launch_bounds__(128) void router_k(const float* __restrict__ x,
                                                const float* __restrict__ rw,
                                                const float* __restrict__ sgw) {
    const int t   = blockIdx.x;
    const int tid = threadIdx.x;
    const float* xr = x + (size_t)t * DD;

    float acc[EE];
#pragma unroll
    for (int e = 0; e < EE; e++) acc[e] = 0.f;
    float gacc = 0.f;

    for (int d = tid; d < DD; d += 128) {
        float xv = xr[d];
        const float* w = rw + (size_t)d * EE;
#pragma unroll
        for (int e = 0; e < EE; e++) acc[e] = fmaf(xv, w[e], acc[e]);
        gacc = fmaf(xv, sgw[d], gacc);
    }

    __shared__ float red[128 * 17];
    __shared__ float redg[128];
    __shared__ float logit[EE];
#pragma unroll
    for (int e = 0; e < EE; e++) red[tid * 17 + e] = acc[e];
    redg[tid] = gacc;
    __syncthreads();

    if (tid < EE) {
        float s = 0.f;
        for (int i = 0; i < 128; i++) s += red[i * 17 + tid];
        logit[tid] = s;
    }
    __syncthreads();

    if (tid == 0) {
        float mx = logit[0];
#pragma unroll
        for (int e = 1; e < EE; e++) mx = fmaxf(mx, logit[e]);
        float p[EE]; float s = 0.f;
#pragma unroll
        for (int e = 0; e < EE; e++) { p[e] = expf(logit[e] - mx); s += p[e]; }
        float inv = 1.f / s;
#pragma unroll
        for (int e = 0; e < EE; e++) { p[e] *= inv; atomicAdd(&g_load[e], p[e]); }

        int i1 = 0;
#pragma unroll
        for (int e = 1; e < EE; e++) if (p[e] > p[i1]) i1 = e;
        int i2 = (i1 == 0) ? 1 : 0;
#pragma unroll
        for (int e = 0; e < EE; e++) if (e != i1 && p[e] > p[i2]) i2 = e;

        float ws = fmaxf(p[i1] + p[i2], 1e-9f);
        float w1 = p[i1] / ws, w2 = p[i2] / ws;

        int q1 = atomicAdd(&g_cnt[i1], 1);
        g_tok[i1 * NT + q1] = t; g_wt[i1 * NT + q1] = w1;
        int q2 = atomicAdd(&g_cnt[i2], 1);
        g_tok[i2 * NT + q2] = t; g_wt[i2 * NT + q2] = w2;

        float gg = 0.f;
        for (int i = 0; i < 128; i++) gg += redg[i];
        g_gs[t] = 1.f / (1.f + expf(-gg));
    }
}

// Shared-expert GEMM1: Hs = silu(x @ Wg) * (x @ Wu).  Wg/Wu are [D, FS] (N-contiguous).
__global__ __launch_bounds__(256) void sgemm1_k(const float* __restrict__ x,
                                                const float* __restrict__ wg,
                                                const float* __restrict__ wu) {
    const int m0 = blockIdx.x * BM;
    const int n0 = blockIdx.y * BN;
    const int tid = threadIdx.x;
    const int tx = tid & 15, ty = tid >> 4;

    __shared__ __align__(16) float As[BK][LDSD];
    __shared__ __align__(16) float Bg[BK][LDSD];
    __shared__ __align__(16) float Bu[BK][LDSD];

    const int alm = tid >> 2, alk = (tid & 3) * 4;   // A loader: row, k-start
    const int blk = tid >> 4, bln = (tid & 15) * 4;  // B loader: k-row, n-start

    float accg[4][4] = {}, accu[4][4] = {};

    for (int k0 = 0; k0 < DD; k0 += BK) {
        float4 av = *(const float4*)(x + (size_t)(m0 + alm) * DD + k0 + alk);
        As[alk + 0][alm] = av.x; As[alk + 1][alm] = av.y;
        As[alk + 2][alm] = av.z; As[alk + 3][alm] = av.w;
        *(float4*)&Bg[blk][bln] = *(const float4*)(wg + (size_t)(k0 + blk) * FSH + n0 + bln);
        *(float4*)&Bu[blk][bln] = *(const float4*)(wu + (size_t)(k0 + blk) * FSH + n0 + bln);
        __syncthreads();
#pragma unroll
        for (int k = 0; k < BK; k++) {
            float4 a  = *(const float4*)&As[k][ty * 4];
            float4 g4 = *(const float4*)&Bg[k][tx * 4];
            float4 u4 = *(const float4*)&Bu[k][tx * 4];
            float avr[4] = {a.x, a.y, a.z, a.w};
            float gvr[4] = {g4.x, g4.y, g4.z, g4.w};
            float uvr[4] = {u4.x, u4.y, u4.z, u4.w};
#pragma unroll
            for (int i = 0; i < 4; i++)
#pragma unroll
                for (int j = 0; j < 4; j++) {
                    accg[i][j] = fmaf(avr[i], gvr[j], accg[i][j]);
                    accu[i][j] = fmaf(avr[i], uvr[j], accu[i][j]);
                }
        }
        __syncthreads();
    }
#pragma unroll
    for (int i = 0; i < 4; i++) {
        int m = m0 + ty * 4 + i;
        float* hr = g_Hs + (size_t)m * FSH + n0 + tx * 4;
#pragma unroll
        for (int j = 0; j < 4; j++) {
            float g = accg[i][j], u = accu[i][j];
            hr[j] = g / (1.f + expf(-g)) * u;
        }
    }
}

// Shared-expert GEMM2: out[t,d] = gate[t] * (Hs @ Wd),  Wd is [FS, D] (N-contiguous).
// Plain store — initializes every output element before expert scatter-adds.
__global__ __launch_bounds__(256) void sgemm2_k(const float* __restrict__ wd,
                                                float* __restrict__ out) {
    const int m0 = blockIdx.x * BM;
    const int n0 = blockIdx.y * BN;
    const int tid = threadIdx.x;
    const int tx = tid & 15, ty = tid >> 4;

    __shared__ __align__(16) float As[BK][LDSD];
    __shared__ __align__(16) float Bs[BK][LDSD];

    const int alm = tid >> 2, alk = (tid & 3) * 4;
    const int blk = tid >> 4, bln = (tid & 15) * 4;

    float acc[4][4] = {};

    for (int k0 = 0; k0 < FSH; k0 += BK) {
        float4 av = *(const float4*)(g_Hs + (size_t)(m0 + alm) * FSH + k0 + alk);
        As[alk + 0][alm] = av.x; As[alk + 1][alm] = av.y;
        As[alk + 2][alm] = av.z; As[alk + 3][alm] = av.w;
        *(float4*)&Bs[blk][bln] = *(const float4*)(wd + (size_t)(k0 + blk) * DD + n0 + bln);
        __syncthreads();
#pragma unroll
        for (int k = 0; k < BK; k++) {
            float4 a = *(const float4*)&As[k][ty * 4];
            float4 b = *(const float4*)&Bs[k][tx * 4];
            float avr[4] = {a.x, a.y, a.z, a.w};
            float bvr[4] = {b.x, b.y, b.z, b.w};
#pragma unroll
            for (int i = 0; i < 4; i++)
#pragma unroll
                for (int j = 0; j < 4; j++)
                    acc[i][j] = fmaf(avr[i], bvr[j], acc[i][j]);
        }
        __syncthreads();
    }
#pragma unroll
    for (int i = 0; i < 4; i++) {
        int m = m0 + ty * 4 + i;
        float gs = g_gs[m];
        float* orow = out + (size_t)m * DD + n0 + tx * 4;
#pragma unroll
        for (int j = 0; j < 4; j++) orow[j] = gs * acc[i][j];
    }
}

// Expert GEMM1: gathered tokens, dual gate/up accumulation, SiLU epilogue -> g_H.
// gate_up_proj[e] is [2F, D] (K-contiguous rows): rows [0,F)=gate, [F,2F)=up.
__global__ __launch_bounds__(256) void egemm1_k(const float* __restrict__ x,
                                                const float* __restrict__ gup) {
    const int e  = blockIdx.z;
    const int ne = g_cnt[e];
    const int m0 = blockIdx.x * BM;
    if (m0 >= ne) return;
    const int f0 = blockIdx.y * BN;
    const int tid = threadIdx.x;
    const int tx = tid & 15, ty = tid >> 4;

    __shared__ __align__(16) float As[BK][LDSD];
    __shared__ __align__(16) float Bg[BK][LDSD];
    __shared__ __align__(16) float Bu[BK][LDSD];
    __shared__ int toks[BM];

    if (tid < BM) {
        int m = m0 + tid;
        toks[tid] = (m < ne) ? g_tok[e * NT + m] : -1;
    }
    __syncthreads();

    const int alm = tid >> 2, alk = (tid & 3) * 4;
    const int tokm = toks[alm];
    const float* base = gup + (size_t)e * (2 * FF) * DD;

    float accg[4][4] = {}, accu[4][4] = {};

    for (int k0 = 0; k0 < DD; k0 += BK) {
        float4 av = make_float4(0.f, 0.f, 0.f, 0.f);
        if (tokm >= 0) av = *(const float4*)(x + (size_t)tokm * DD + k0 + alk);
        As[alk + 0][alm] = av.x; As[alk + 1][alm] = av.y;
        As[alk + 2][alm] = av.z; As[alk + 3][alm] = av.w;
        float4 bg = *(const float4*)(base + (size_t)(f0 + alm) * DD + k0 + alk);
        Bg[alk + 0][alm] = bg.x; Bg[alk + 1][alm] = bg.y;
        Bg[alk + 2][alm] = bg.z; Bg[alk + 3][alm] = bg.w;
        float4 bu = *(const float4*)(base + (size_t)(FF + f0 + alm) * DD + k0 + alk);
        Bu[alk + 0][alm] = bu.x; Bu[alk + 1][alm] = bu.y;
        Bu[alk + 2][alm] = bu.z; Bu[alk + 3][alm] = bu.w;
        __syncthreads();
#pragma unroll
        for (int k = 0; k < BK; k++) {
            float4 a  = *(const float4*)&As[k][ty * 4];
            float4 g4 = *(const float4*)&Bg[k][tx * 4];
            float4 u4 = *(const float4*)&Bu[k][tx * 4];
            float avr[4] = {a.x, a.y, a.z, a.w};
            float gvr[4] = {g4.x, g4.y, g4.z, g4.w};
            float uvr[4] = {u4.x, u4.y, u4.z, u4.w};
#pragma unroll
            for (int i = 0; i < 4; i++)
#pragma unroll
                for (int j = 0; j < 4; j++) {
                    accg[i][j] = fmaf(avr[i], gvr[j], accg[i][j]);
                    accu[i][j] = fmaf(avr[i], uvr[j], accu[i][j]);
                }
        }
        __syncthreads();
    }
#pragma unroll
    for (int i = 0; i < 4; i++) {
        int idx = m0 + ty * 4 + i;
        if (idx < ne) {
            float* hr = g_H + ((size_t)e * NT + idx) * FF + f0 + tx * 4;
#pragma unroll
            for (int j = 0; j < 4; j++) {
                float g = accg[i][j], u = accu[i][j];
                hr[j] = g / (1.f + expf(-g)) * u;
            }
        }
    }
}

// Expert GEMM2: out += w_token * (H_e @ Wd_e^T). down_proj[e] is [D, F] (K-contiguous rows).
__global__ __launch_bounds__(256) void egemm2_k(const float* __restrict__ wd,
                                                float* __restrict__ out) {
    const int e  = blockIdx.z;
    const int ne = g_cnt[e];
    const int m0 = blockIdx.x * BM;
    if (m0 >= ne) return;
    const int d0 = blockIdx.y * BN;
    const int tid = threadIdx.x;
    const int tx = tid & 15, ty = tid >> 4;

    __shared__ __align__(16) float As[BK][LDSD];
    __shared__ __align__(16) float Bs[BK][LDSD];

    const int alm = tid >> 2, alk = (tid & 3) * 4;
    const float* Ab = g_H + (size_t)e * NT * FF;
    const float* Bb = wd + (size_t)e * DD * FF;

    float acc[4][4] = {};

    for (int k0 = 0; k0 < FF; k0 += BK) {
        float4 av = *(const float4*)(Ab + (size_t)(m0 + alm) * FF + k0 + alk);
        As[alk + 0][alm] = av.x; As[alk + 1][alm] = av.y;
        As[alk + 2][alm] = av.z; As[alk + 3][alm] = av.w;
        float4 bv = *(const float4*)(Bb + (size_t)(d0 + alm) * FF + k0 + alk);
        Bs[alk + 0][alm] = bv.x; Bs[alk + 1][alm] = bv.y;
        Bs[alk + 2][alm] = bv.z; Bs[alk + 3][alm] = bv.w;
        __syncthreads();
#pragma unroll
        for (int k = 0; k < BK; k++) {
            float4 a = *(const float4*)&As[k][ty * 4];
            float4 b = *(const float4*)&Bs[k][tx * 4];
            float avr[4] = {a.x, a.y, a.z, a.w};
            float bvr[4] = {b.x, b.y, b.z, b.w};
#pragma unroll
            for (int i = 0; i < 4; i++)
#pragma unroll
                for (int j = 0; j < 4; j++)
                    acc[i][j] = fmaf(avr[i], bvr[j], acc[i][j]);
        }
        __syncthreads();
    }
#pragma unroll
    for (int i = 0; i < 4; i++) {
        int idx = m0 + ty * 4 + i;
        if (idx < ne) {
            int   t = g_tok[e * NT + idx];
            float w = g_wt[e * NT + idx];
            float* orow = out + (size_t)t * DD + d0 + tx * 4;
#pragma unroll
            for (int j = 0; j < 4; j++)
                atomicAdd(&orow[j], w * acc[i][j]);
        }
    }
}

__global__ void aux_k(float* __restrict__ out) {
    int e = threadIdx.x;
    float v = 0.f;
    if (e < EE) {
        float l = g_load[e] / (float)NT - 1.0f / (float)EE;
        v = l * l;
    }
#pragma unroll
    for (int off = 16; off > 0; off >>= 1)
        v += __shfl_xor_sync(0xFFFFFFFFu, v, off);
    if (threadIdx.x == 0) out[(size_t)NT * DD] = 0.001f * v;
}

// ---------------------------------------------------------------------------------------
extern "C" void kernel_launch(void* const* d_in, const int* in_sizes, int n_in,
                              void* d_out, int out_size) {
    (void)in_sizes; (void)n_in;
    const float* x     = (const float*)d_in[0];
    const float* gup   = (const float*)d_in[1];
    const float* dwn   = (const float*)d_in[2];
    const float* rw    = (const float*)d_in[3];
    const float* sgate = (const float*)d_in[4];
    const float* sup   = (const float*)d_in[5];
    const float* sdown = (const float*)d_in[6];
    const float* shg   = (const float*)d_in[7];
    float* out = (float*)d_out;

    zero_k<<<1, 32>>>();
    router_k<<<NT, 128>>>(x, rw, shg);
    sgemm1_k<<<dim3(NT / BM, FSH / BN), 256>>>(x, sgate, sup);
    sgemm2_k<<<dim3(NT / BM, DD / BN), 256>>>(sdown, out);
    egemm1_k<<<dim3(NT / BM, FF / BN, EE), 256>>>(x, gup);
    egemm2_k<<<dim3(NT / BM, DD / BN, EE), 256>>>(dwn, out);
    if (out_size > NT * DD) aux_k<<<1, 32>>>(out);
}

// round 2
// speedup vs baseline: 1.2072x; 1.2072x over previous
#include <cuda_runtime.h>
#include <math.h>

#define NT   2048      // B*T tokens
#define DD   1024      // model dim
#define EE   16        // experts
#define FF   512       // expert ffn dim
#define FSH  2048      // shared expert ffn dim

// ---------------- scratch (static device globals; no runtime allocation) ----------------
__device__ int   g_cnt[EE];
__device__ float g_load[EE];
__device__ int   g_tok[EE * NT];
__device__ float g_wt[EE * NT];
__device__ float g_gs[NT];
__device__ float g_H[(size_t)EE * NT * FF];   // expert hidden, per-expert packed rows
__device__ float g_Hs[(size_t)NT * FSH];      // shared-expert hidden

// ---------------------------------------------------------------------------------------
__global__ void zero_k() {
    int i = threadIdx.x;
    if (i < EE) { g_cnt[i] = 0; g_load[i] = 0.f; }
}

// Router: one block (128 thr) per token. Warp-shuffle reduction for logits + gate.
__global__ __launch_bounds__(128) void router_k(const float* __restrict__ x,
                                                const float* __restrict__ rw,
                                                const float* __restrict__ sgw) {
    const int t   = blockIdx.x;
    const int tid = threadIdx.x;
    const float* xr = x + (size_t)t * DD;

    float acc[EE];
#pragma unroll
    for (int e = 0; e < EE; e++) acc[e] = 0.f;
    float gacc = 0.f;

    for (int d = tid; d < DD; d += 128) {
        float xv = xr[d];
        const float* w = rw + (size_t)d * EE;
#pragma unroll
        for (int e = 0; e < EE; e++) acc[e] = fmaf(xv, w[e], acc[e]);
        gacc = fmaf(xv, sgw[d], gacc);
    }

#pragma unroll
    for (int off = 16; off > 0; off >>= 1) {
#pragma unroll
        for (int e = 0; e < EE; e++) acc[e] += __shfl_xor_sync(0xFFFFFFFFu, acc[e], off);
        gacc += __shfl_xor_sync(0xFFFFFFFFu, gacc, off);
    }

    __shared__ float sacc[4][EE];
    __shared__ float sg[4];
    const int w = tid >> 5, l = tid & 31;
    if (l == 0) {
#pragma unroll
        for (int e = 0; e < EE; e++) sacc[w][e] = acc[e];
        sg[w] = gacc;
    }
    __syncthreads();

    if (tid == 0) {
        float p[EE];
        float mx = -1e30f;
#pragma unroll
        for (int e = 0; e < EE; e++) {
            p[e] = sacc[0][e] + sacc[1][e] + sacc[2][e] + sacc[3][e];
            mx = fmaxf(mx, p[e]);
        }
        float s = 0.f;
#pragma unroll
        for (int e = 0; e < EE; e++) { p[e] = expf(p[e] - mx); s += p[e]; }
        float inv = 1.f / s;
#pragma unroll
        for (int e = 0; e < EE; e++) { p[e] *= inv; atomicAdd(&g_load[e], p[e]); }

        int i1 = 0;
#pragma unroll
        for (int e = 1; e < EE; e++) if (p[e] > p[i1]) i1 = e;
        int i2 = (i1 == 0) ? 1 : 0;
#pragma unroll
        for (int e = 0; e < EE; e++) if (e != i1 && p[e] > p[i2]) i2 = e;

        float ws = fmaxf(p[i1] + p[i2], 1e-9f);
        float w1 = p[i1] / ws, w2 = p[i2] / ws;

        int q1 = atomicAdd(&g_cnt[i1], 1);
        g_tok[i1 * NT + q1] = t; g_wt[i1 * NT + q1] = w1;
        int q2 = atomicAdd(&g_cnt[i2], 1);
        g_tok[i2 * NT + q2] = t; g_wt[i2 * NT + q2] = w2;

        float gg = sg[0] + sg[1] + sg[2] + sg[3];
        g_gs[t] = 1.f / (1.f + expf(-gg));
    }
}

// ============== dual-B GEMM, 128x64 tile, BK=16, 256 threads, 8x4 microtile =============
// Shared-expert GEMM1: Hs = silu(x @ Wg) * (x @ Wu).  Wg/Wu [D, FS] (N-contiguous rows).
__global__ __launch_bounds__(256, 1) void sgemm1_k(const float* __restrict__ x,
                                                   const float* __restrict__ wg,
                                                   const float* __restrict__ wu) {
    const int m0 = blockIdx.x * 128;
    const int n0 = blockIdx.y * 64;
    const int tid = threadIdx.x;
    const int tx = tid & 15, ty = tid >> 4;

    __shared__ __align__(16) float As[16][132];
    __shared__ __align__(16) float Bg[16][68];
    __shared__ __align__(16) float Bu[16][68];

    const int ar = tid >> 1, akq = (tid & 1) * 8;     // A: row 0..127, k-start {0,8}
    const int bkr = tid >> 4, bnq = (tid & 15) * 4;   // B: k-row 0..15, n-start

    const float* Ap = x + (size_t)(m0 + ar) * DD + akq;
    const float* Gp = wg + (size_t)bkr * FSH + n0 + bnq;
    const float* Up = wu + (size_t)bkr * FSH + n0 + bnq;

    float4 pa0 = *(const float4*)(Ap);
    float4 pa1 = *(const float4*)(Ap + 4);
    float4 pg  = *(const float4*)(Gp);
    float4 pu  = *(const float4*)(Up);

    float accg[8][4] = {}, accu[8][4] = {};

    for (int kt = 0; kt < DD / 16; kt++) {
        As[akq + 0][ar] = pa0.x; As[akq + 1][ar] = pa0.y;
        As[akq + 2][ar] = pa0.z; As[akq + 3][ar] = pa0.w;
        As[akq + 4][ar] = pa1.x; As[akq + 5][ar] = pa1.y;
        As[akq + 6][ar] = pa1.z; As[akq + 7][ar] = pa1.w;
        *(float4*)&Bg[bkr][bnq] = pg;
        *(float4*)&Bu[bkr][bnq] = pu;
        __syncthreads();
        if (kt < DD / 16 - 1) {
            pa0 = *(const float4*)(Ap + (kt + 1) * 16);
            pa1 = *(const float4*)(Ap + (kt + 1) * 16 + 4);
            pg  = *(const float4*)(Gp + (size_t)(kt + 1) * 16 * FSH);
            pu  = *(const float4*)(Up + (size_t)(kt + 1) * 16 * FSH);
        }
#pragma unroll
        for (int k = 0; k < 16; k++) {
            float4 a0 = *(const float4*)&As[k][ty * 4];
            float4 a1 = *(const float4*)&As[k][64 + ty * 4];
            float4 g4 = *(const float4*)&Bg[k][tx * 4];
            float4 u4 = *(const float4*)&Bu[k][tx * 4];
            float am[8] = {a0.x, a0.y, a0.z, a0.w, a1.x, a1.y, a1.z, a1.w};
            float gv[4] = {g4.x, g4.y, g4.z, g4.w};
            float uv[4] = {u4.x, u4.y, u4.z, u4.w};
#pragma unroll
            for (int mi = 0; mi < 8; mi++)
#pragma unroll
                for (int nj = 0; nj < 4; nj++) {
                    accg[mi][nj] = fmaf(am[mi], gv[nj], accg[mi][nj]);
                    accu[mi][nj] = fmaf(am[mi], uv[nj], accu[mi][nj]);
                }
        }
        __syncthreads();
    }
#pragma unroll
    for (int h = 0; h < 2; h++)
#pragma unroll
        for (int mi = 0; mi < 4; mi++) {
            int m = m0 + h * 64 + ty * 4 + mi;
            float* hr = g_Hs + (size_t)m * FSH + n0 + tx * 4;
#pragma unroll
            for (int j = 0; j < 4; j++) {
                float g = accg[h * 4 + mi][j], u = accu[h * 4 + mi][j];
                hr[j] = g / (1.f + expf(-g)) * u;
            }
        }
}

// Expert GEMM1 (gathered A, transposed B): hidden = silu(x@Wg_e^T)*(x@Wu_e^T) -> g_H.
// gate_up_proj[e] is [2F, D] K-contiguous rows (rows [0,F)=gate, [F,2F)=up).
__global__ __launch_bounds__(256, 1) void egemm1_k(const float* __restrict__ x,
                                                   const float* __restrict__ gup) {
    const int e  = blockIdx.z;
    const int ne = g_cnt[e];
    const int m0 = blockIdx.x * 128;
    if (m0 >= ne) return;
    const int f0 = blockIdx.y * 64;
    const int tid = threadIdx.x;
    const int tx = tid & 15, ty = tid >> 4;

    __shared__ __align__(16) float As[16][132];
    __shared__ __align__(16) float Bg[16][68];
    __shared__ __align__(16) float Bu[16][68];
    __shared__ int toks[128];

    if (tid < 128) {
        int m = m0 + tid;
        toks[tid] = (m < ne) ? g_tok[e * NT + m] : -1;
    }
    __syncthreads();

    const int ar = tid >> 1, akq = (tid & 1) * 8;
    const int br = tid >> 2, bkq = (tid & 3) * 4;   // B: f-row 0..63, k-start

    const int tokm = toks[ar];
    const float* base = gup + (size_t)e * (2 * FF) * DD;
    const float* Ap = (tokm >= 0) ? (x + (size_t)tokm * DD + akq) : nullptr;
    const float* Gp = base + (size_t)(f0 + br) * DD + bkq;
    const float* Up = base + (size_t)(FF + f0 + br) * DD + bkq;

    float4 z4 = make_float4(0.f, 0.f, 0.f, 0.f);
    float4 pa0 = z4, pa1 = z4;
    if (tokm >= 0) { pa0 = *(const float4*)(Ap); pa1 = *(const float4*)(Ap + 4); }
    float4 pg = *(const float4*)(Gp);
    float4 pu = *(const float4*)(Up);

    float accg[8][4] = {}, accu[8][4] = {};

    for (int kt = 0; kt < DD / 16; kt++) {
        As[akq + 0][ar] = pa0.x; As[akq + 1][ar] = pa0.y;
        As[akq + 2][ar] = pa0.z; As[akq + 3][ar] = pa0.w;
        As[akq + 4][ar] = pa1.x; As[akq + 5][ar] = pa1.y;
        As[akq + 6][ar] = pa1.z; As[akq + 7][ar] = pa1.w;
        Bg[bkq + 0][br] = pg.x; Bg[bkq + 1][br] = pg.y;
        Bg[bkq + 2][br] = pg.z; Bg[bkq + 3][br] = pg.w;
        Bu[bkq + 0][br] = pu.x; Bu[bkq + 1][br] = pu.y;
        Bu[bkq + 2][br] = pu.z; Bu[bkq + 3][br] = pu.w;
        __syncthreads();
        if (kt < DD / 16 - 1) {
            if (tokm >= 0) {
                pa0 = *(const float4*)(Ap + (kt + 1) * 16);
                pa1 = *(const float4*)(Ap + (kt + 1) * 16 + 4);
            }
            pg = *(const float4*)(Gp + (kt + 1) * 16);
            pu = *(const float4*)(Up + (kt + 1) * 16);
        }
#pragma unroll
        for (int k = 0; k < 16; k++) {
            float4 a0 = *(const float4*)&As[k][ty * 4];
            float4 a1 = *(const float4*)&As[k][64 + ty * 4];
            float4 g4 = *(const float4*)&Bg[k][tx * 4];
            float4 u4 = *(const float4*)&Bu[k][tx * 4];
            float am[8] = {a0.x, a0.y, a0.z, a0.w, a1.x, a1.y, a1.z, a1.w};
            float gv[4] = {g4.x, g4.y, g4.z, g4.w};
            float uv[4] = {u4.x, u4.y, u4.z, u4.w};
#pragma unroll
            for (int mi = 0; mi < 8; mi++)
#pragma unroll
                for (int nj = 0; nj < 4; nj++) {
                    accg[mi][nj] = fmaf(am[mi], gv[nj], accg[mi][nj]);
                    accu[mi][nj] = fmaf(am[mi], uv[nj], accu[mi][nj]);
                }
        }
        __syncthreads();
    }
#pragma unroll
    for (int h = 0; h < 2; h++)
#pragma unroll
        for (int mi = 0; mi < 4; mi++) {
            int idx = m0 + h * 64 + ty * 4 + mi;
            if (idx < ne) {
                float* hr = g_H + ((size_t)e * NT + idx) * FF + f0 + tx * 4;
#pragma unroll
                for (int j = 0; j < 4; j++) {
                    float g = accg[h * 4 + mi][j], u = accu[h * 4 + mi][j];
                    hr[j] = g / (1.f + expf(-g)) * u;
                }
            }
        }
}

// ============== single-B GEMM, 64x128 tile, BK=16, 256 threads, 4x8 microtile ===========
// Shared-expert GEMM2: out[t,d] = gate[t] * (Hs @ Wd).  Wd [FS, D] (N-contiguous rows).
__global__ __launch_bounds__(256, 1) void sgemm2_k(const float* __restrict__ wd,
                                                   float* __restrict__ out) {
    const int m0 = blockIdx.x * 64;
    const int n0 = blockIdx.y * 128;
    const int tid = threadIdx.x;
    const int tx = tid & 15, ty = tid >> 4;

    __shared__ __align__(16) float As[16][68];
    __shared__ __align__(16) float Bs[16][132];

    const int ar = tid >> 2, akq = (tid & 3) * 4;    // A: row 0..63
    const int bkr = tid >> 4, bnq = (tid & 15) * 4;  // B: k-row 0..15, two float4 (nq, nq+64)

    const float* Ap = g_Hs + (size_t)(m0 + ar) * FSH + akq;
    const float* Bp = wd + (size_t)bkr * DD + n0 + bnq;

    float4 pa  = *(const float4*)(Ap);
    float4 pb0 = *(const float4*)(Bp);
    float4 pb1 = *(const float4*)(Bp + 64);

    float acc[4][8] = {};

    for (int kt = 0; kt < FSH / 16; kt++) {
        As[akq + 0][ar] = pa.x; As[akq + 1][ar] = pa.y;
        As[akq + 2][ar] = pa.z; As[akq + 3][ar] = pa.w;
        *(float4*)&Bs[bkr][bnq]      = pb0;
        *(float4*)&Bs[bkr][64 + bnq] = pb1;
        __syncthreads();
        if (kt < FSH / 16 - 1) {
            pa  = *(const float4*)(Ap + (kt + 1) * 16);
            pb0 = *(const float4*)(Bp + (size_t)(kt + 1) * 16 * DD);
            pb1 = *(const float4*)(Bp + (size_t)(kt + 1) * 16 * DD + 64);
        }
#pragma unroll
        for (int k = 0; k < 16; k++) {
            float4 a  = *(const float4*)&As[k][ty * 4];
            float4 b0 = *(const float4*)&Bs[k][tx * 4];
            float4 b1 = *(const float4*)&Bs[k][64 + tx * 4];
            float am[4] = {a.x, a.y, a.z, a.w};
            float bv[8] = {b0.x, b0.y, b0.z, b0.w, b1.x, b1.y, b1.z, b1.w};
#pragma unroll
            for (int mi = 0; mi < 4; mi++)
#pragma unroll
                for (int nj = 0; nj < 8; nj++)
                    acc[mi][nj] = fmaf(am[mi], bv[nj], acc[mi][nj]);
        }
        __syncthreads();
    }
#pragma unroll
    for (int mi = 0; mi < 4; mi++) {
        int m = m0 + ty * 4 + mi;
        float gs = g_gs[m];
        float* orow = out + (size_t)m * DD + n0;
#pragma unroll
        for (int h = 0; h < 2; h++)
#pragma unroll
            for (int j = 0; j < 4; j++)
                orow[h * 64 + tx * 4 + j] = gs * acc[mi][h * 4 + j];
    }
}

// Expert GEMM2: out += w_token * (H_e @ Wd_e^T). down_proj[e] is [D, F] K-contiguous rows.
__global__ __launch_bounds__(256, 1) void egemm2_k(const float* __restrict__ wd,
                                                   float* __restrict__ out) {
    const int e  = blockIdx.z;
    const int ne = g_cnt[e];
    const int m0 = blockIdx.x * 64;
    if (m0 >= ne) return;
    const int d0 = blockIdx.y * 128;
    const int tid = threadIdx.x;
    const int tx = tid & 15, ty = tid >> 4;

    __shared__ __align__(16) float As[16][68];
    __shared__ __align__(16) float Bs[16][132];

    const int ar = tid >> 2, akq = (tid & 3) * 4;    // A: row 0..63, k-start
    const int br = tid >> 1, bkq = (tid & 1) * 8;    // B: d-row 0..127, k-start {0,8}

    const float* Ap = g_H + ((size_t)e * NT + m0 + ar) * FF + akq;
    const float* Bp = wd + (size_t)e * DD * FF + (size_t)(d0 + br) * FF + bkq;

    float4 pa  = *(const float4*)(Ap);
    float4 pb0 = *(const float4*)(Bp);
    float4 pb1 = *(const float4*)(Bp + 4);

    float acc[4][8] = {};

    for (int kt = 0; kt < FF / 16; kt++) {
        As[akq + 0][ar] = pa.x; As[akq + 1][ar] = pa.y;
        As[akq + 2][ar] = pa.z; As[akq + 3][ar] = pa.w;
        Bs[bkq + 0][br] = pb0.x; Bs[bkq + 1][br] = pb0.y;
        Bs[bkq + 2][br] = pb0.z; Bs[bkq + 3][br] = pb0.w;
        Bs[bkq + 4][br] = pb1.x; Bs[bkq + 5][br] = pb1.y;
        Bs[bkq + 6][br] = pb1.z; Bs[bkq + 7][br] = pb1.w;
        __syncthreads();
        if (kt < FF / 16 - 1) {
            pa  = *(const float4*)(Ap + (kt + 1) * 16);
            pb0 = *(const float4*)(Bp + (kt + 1) * 16);
            pb1 = *(const float4*)(Bp + (kt + 1) * 16 + 4);
        }
#pragma unroll
        for (int k = 0; k < 16; k++) {
            float4 a  = *(const float4*)&As[k][ty * 4];
            float4 b0 = *(const float4*)&Bs[k][tx * 4];
            float4 b1 = *(const float4*)&Bs[k][64 + tx * 4];
            float am[4] = {a.x, a.y, a.z, a.w};
            float bv[8] = {b0.x, b0.y, b0.z, b0.w, b1.x, b1.y, b1.z, b1.w};
#pragma unroll
            for (int mi = 0; mi < 4; mi++)
#pragma unroll
                for (int nj = 0; nj < 8; nj++)
                    acc[mi][nj] = fmaf(am[mi], bv[nj], acc[mi][nj]);
        }
        __syncthreads();
    }
#pragma unroll
    for (int mi = 0; mi < 4; mi++) {
        int idx = m0 + ty * 4 + mi;
        if (idx < ne) {
            int   t = g_tok[e * NT + idx];
            float w = g_wt[e * NT + idx];
            float* orow = out + (size_t)t * DD + d0;
#pragma unroll
            for (int h = 0; h < 2; h++)
#pragma unroll
                for (int j = 0; j < 4; j++)
                    atomicAdd(&orow[h * 64 + tx * 4 + j], w * acc[mi][h * 4 + j]);
        }
    }
}

__global__ void aux_k(float* __restrict__ out) {
    int e = threadIdx.x;
    float v = 0.f;
    if (e < EE) {
        float l = g_load[e] / (float)NT - 1.0f / (float)EE;
        v = l * l;
    }
#pragma unroll
    for (int off = 16; off > 0; off >>= 1)
        v += __shfl_xor_sync(0xFFFFFFFFu, v, off);
    if (threadIdx.x == 0) out[(size_t)NT * DD] = 0.001f * v;
}

// ---------------------------------------------------------------------------------------
extern "C" void kernel_launch(void* const* d_in, const int* in_sizes, int n_in,
                              void* d_out, int out_size) {
    (void)in_sizes; (void)n_in;
    const float* x     = (const float*)d_in[0];
    const float* gup   = (const float*)d_in[1];
    const float* dwn   = (const float*)d_in[2];
    const float* rw    = (const float*)d_in[3];
    const float* sgate = (const float*)d_in[4];
    const float* sup   = (const float*)d_in[5];
    const float* sdown = (const float*)d_in[6];
    const float* shg   = (const float*)d_in[7];
    float* out = (float*)d_out;

    zero_k<<<1, 32>>>();
    router_k<<<NT, 128>>>(x, rw, shg);
    sgemm1_k<<<dim3(NT / 128, FSH / 64), 256>>>(x, sgate, sup);
    sgemm2_k<<<dim3(NT / 64, DD / 128), 256>>>(sdown, out);
    egemm1_k<<<dim3(NT / 128, FF / 64, EE), 256>>>(x, gup);
    egemm2_k<<<dim3(NT / 64, DD / 128, EE), 256>>>(dwn, out);
    if (out_size > NT * DD) aux_k<<<1, 32>>>(out);
}